// round 12
// baseline (speedup 1.0000x reference)
#include <cuda_runtime.h>
#include <math.h>

// ---------------- scratch (no allocs allowed) ----------------
#define MAX_T (64 * 4096)
#define MAX_B 64
#define MAX_K 1024
__device__ float g_dot[MAX_T];          // per-node dot(logits, proj)
__device__ int   g_idx[MAX_B * MAX_K];  // selected global node indices per graph
__device__ int   g_done[MAX_B];         // per-graph arrival counters (zero at load;
                                        // each selecting block resets its own -> replay-safe)

// ---------------- shared state for the inline select ----------------
struct SelSM {
    unsigned keys[4096];
    unsigned hist[256];
    unsigned warpTot[8];
    unsigned s_chosen, s_need;
    int cntGT, cntEQ;
};

// ---------------- inline per-graph radix select (512 threads) ----------------
// 4x 8-bit MSB-first radix passes; warp-aggregated histogram (Gaussian keys
// cluster in ~14 exponent bins); ballot-aggregated compaction. Zeroes the
// graph's output row. Reads dots via __ldcg (written by other blocks).
__device__ void select_graph(int b, int N, int K, int D,
                             float* __restrict__ out, SelSM& sm) {
    const int TB = 512;
    int tid = threadIdx.x;
    int lane = tid & 31, warp = tid >> 5;

    for (int i = tid; i < D; i += TB) out[(size_t)b * D + i] = 0.0f;

    for (int i = tid; i < N; i += TB) {
        unsigned u = __float_as_uint(__ldcg(&g_dot[(size_t)b * N + i]));
        u ^= (u >> 31) ? 0xFFFFFFFFu : 0x80000000u;  // order-preserving
        sm.keys[i] = u;
    }
    if (tid == 0) sm.s_need = (unsigned)K;
    __syncthreads();

    unsigned prefix = 0, mask = 0;
#pragma unroll
    for (int pass = 0; pass < 4; pass++) {
        int shift = 24 - 8 * pass;
        unsigned need = sm.s_need;
        if (tid < 256) sm.hist[tid] = 0;
        __syncthreads();
        for (int i = tid; i < N; i += TB) {
            unsigned kk = sm.keys[i];
            bool pred = ((kk & mask) == prefix);
            unsigned bin = (kk >> shift) & 0xFFu;
            unsigned act = __ballot_sync(0xFFFFFFFFu, pred);
            if (pred) {
                unsigned mm = __match_any_sync(act, bin);
                int leader = __ffs(mm) - 1;
                if (lane == leader) atomicAdd(&sm.hist[bin], (unsigned)__popc(mm));
            }
        }
        __syncthreads();
        // two-level suffix scan over 256 bins (warps 0..7)
        if (warp < 8) {
            unsigned sum = sm.hist[warp * 32 + lane];
#pragma unroll
            for (int o = 1; o < 32; o <<= 1) {
                unsigned t = __shfl_down_sync(0xFFFFFFFFu, sum, o);
                if (lane + o < 32) sum += t;
            }
            if (lane == 0) sm.warpTot[warp] = sum;
            __syncwarp();
            sm.hist[warp * 32 + lane] = sum;   // intra-warp inclusive suffix
        }
        __syncthreads();
        if (tid < 256) {
            unsigned add = 0;
            int myw = tid >> 5;
#pragma unroll
            for (int w = 0; w < 8; w++)
                if (w > myw) add += sm.warpTot[w];
            unsigned st = sm.hist[tid] + add;
            unsigned sn;
            if (tid == 255) sn = 0;
            else if ((tid & 31) == 31) sn = add;
            else sn = sm.hist[tid + 1] + add;
            if (st >= need && sn < need) {   // unique largest bin with suffix >= need
                sm.s_chosen = (unsigned)tid;
                sm.s_need = need - sn;
            }
        }
        __syncthreads();
        prefix |= sm.s_chosen << shift;
        mask   |= 0xFFu << shift;
        __syncthreads();
    }

    unsigned thr = prefix;  // exact key of the k-th largest
    if (tid == 0) {
        sm.cntGT = 0;
        sm.cntEQ = K - (int)sm.s_need;  // strictly-greater count; ties fill [G, K)
    }
    __syncthreads();

    int* lst = g_idx + (size_t)b * K;
    unsigned lmLT = (1u << lane) - 1u;
    for (int i = tid; i < N; i += TB) {
        unsigned kk = sm.keys[i];
        bool isGT = (kk > thr), isEQ = (kk == thr);
        unsigned bGT = __ballot_sync(0xFFFFFFFFu, isGT);
        if (bGT) {
            int base = 0;
            int leader = __ffs(bGT) - 1;
            if (lane == leader) base = atomicAdd(&sm.cntGT, __popc(bGT));
            base = __shfl_sync(0xFFFFFFFFu, base, leader);
            if (isGT) lst[base + __popc(bGT & lmLT)] = b * N + i;
        }
        unsigned bEQ = __ballot_sync(0xFFFFFFFFu, isEQ);
        if (bEQ) {
            int base = 0;
            int leader = __ffs(bEQ) - 1;
            if (lane == leader) base = atomicAdd(&sm.cntEQ, __popc(bEQ));
            base = __shfl_sync(0xFFFFFFFFu, base, leader);
            if (isEQ) {
                int p = base + __popc(bEQ & lmLT);
                if (p < K) lst[p] = b * N + i;
            }
        }
    }
}

// ---------------- kernel 1: dot + fused last-block select ----------------
// 512 threads = 16 warps x 4 rows = 64 rows/block; blocksPerGraph = N/64.
// After a block writes its dots, it bumps its graph's counter; the LAST
// block of each graph runs the radix select inline (hidden under remaining
// dot waves). Counter is self-resetting -> graph-replay safe.
__global__ void __launch_bounds__(512)
dot_select_kernel(const float* __restrict__ logits,
                  const float* __restrict__ proj,
                  float* __restrict__ out,
                  int N, int K, int D, int blocksPerGraph) {
    __shared__ float4 pS[64];
    __shared__ SelSM sm;
    __shared__ int s_last;

    int tid = threadIdx.x;
    if (tid < 64) pS[tid] = reinterpret_cast<const float4*>(proj)[tid];
    __syncthreads();

    int warp = tid >> 5, lane = tid & 31;
    int row0 = (blockIdx.x * 16 + warp) * 4;

    {
        const float4* rp = reinterpret_cast<const float4*>(logits) + (size_t)row0 * 64;
        float4 a[4], c[4];
#pragma unroll
        for (int r = 0; r < 4; r++) {
            a[r] = rp[(size_t)r * 64 + lane];
            c[r] = rp[(size_t)r * 64 + lane + 32];
        }
        float4 pa = pS[lane];
        float4 pc = pS[lane + 32];

        float s[4];
#pragma unroll
        for (int r = 0; r < 4; r++) {
            s[r] = a[r].x * pa.x + a[r].y * pa.y + a[r].z * pa.z + a[r].w * pa.w
                 + c[r].x * pc.x + c[r].y * pc.y + c[r].z * pc.z + c[r].w * pc.w;
#pragma unroll
            for (int o = 16; o; o >>= 1) s[r] += __shfl_xor_sync(0xFFFFFFFFu, s[r], o);
        }
        if (lane < 4) g_dot[row0 + lane] = s[lane];
    }

    int graph = blockIdx.x / blocksPerGraph;

    // publish dots, then count arrivals for this graph
    __threadfence();
    if (tid == 0) {
        int old = atomicAdd(&g_done[graph], 1);
        int last = (old == blocksPerGraph - 1);
        if (last) g_done[graph] = 0;   // reset for next replay (no other block touches it now)
        s_last = last;
    }
    __syncthreads();

    if (s_last) select_graph(graph, N, K, D, out, sm);
}

// ---------------- kernel 2: gather + segment sum (pipelined, GSPLIT=16) ----------
// 1024 blocks = 64 graphs x 16 slices; ~52 rows (52KB) per block. 256 threads
// = 4 row-groups x 64 lanes; each group streams ~13 rows through a 4-slot
// register pipeline (4 float4 outstanding, statically indexed).
#define GSPLIT 16
__global__ void __launch_bounds__(256)
gather_sum_kernel(const float* __restrict__ logits,
                  const int* __restrict__ idxList,
                  float* __restrict__ out,
                  int K, int D, int bBase) {
    __shared__ int sidx[64];
    __shared__ float4 part[4][64];

    int b = bBase + blockIdx.x / GSPLIT;
    int s = blockIdx.x % GSPLIT;
    int tid = threadIdx.x;
    int grp = tid >> 6;        // 0..3
    int l64 = tid & 63;        // float4 column within row

    int per = (K + GSPLIT - 1) / GSPLIT;          // 52 for K=820
    int r0 = s * per;
    int cnt = min(K, r0 + per) - r0;              // 40..52

    if (tid < cnt) sidx[tid] = idxList[(size_t)b * K + r0 + tid];
    __syncthreads();

    const float4* lg4 = reinterpret_cast<const float4*>(logits);
    int nD4 = D >> 2;  // 64

    int nj = (cnt > grp) ? ((cnt - grp + 3) >> 2) : 0;

    float4 buf0, buf1, buf2, buf3;
    if (0 < nj) buf0 = lg4[(size_t)sidx[grp +  0] * nD4 + l64];
    if (1 < nj) buf1 = lg4[(size_t)sidx[grp +  4] * nD4 + l64];
    if (2 < nj) buf2 = lg4[(size_t)sidx[grp +  8] * nD4 + l64];
    if (3 < nj) buf3 = lg4[(size_t)sidx[grp + 12] * nD4 + l64];

    float4 acc0 = make_float4(0.f, 0.f, 0.f, 0.f);
    float4 acc1 = make_float4(0.f, 0.f, 0.f, 0.f);

    int j = 0;
#pragma unroll 1
    for (; j + 4 <= nj; j += 4) {
        acc0.x += buf0.x; acc0.y += buf0.y; acc0.z += buf0.z; acc0.w += buf0.w;
        if (j + 4 < nj) buf0 = lg4[(size_t)sidx[grp + 4 * (j + 4)] * nD4 + l64];
        acc1.x += buf1.x; acc1.y += buf1.y; acc1.z += buf1.z; acc1.w += buf1.w;
        if (j + 5 < nj) buf1 = lg4[(size_t)sidx[grp + 4 * (j + 5)] * nD4 + l64];
        acc0.x += buf2.x; acc0.y += buf2.y; acc0.z += buf2.z; acc0.w += buf2.w;
        if (j + 6 < nj) buf2 = lg4[(size_t)sidx[grp + 4 * (j + 6)] * nD4 + l64];
        acc1.x += buf3.x; acc1.y += buf3.y; acc1.z += buf3.z; acc1.w += buf3.w;
        if (j + 7 < nj) buf3 = lg4[(size_t)sidx[grp + 4 * (j + 7)] * nD4 + l64];
    }
    int rem = nj - j;
    if (rem > 0) { acc0.x += buf0.x; acc0.y += buf0.y; acc0.z += buf0.z; acc0.w += buf0.w; }
    if (rem > 1) { acc1.x += buf1.x; acc1.y += buf1.y; acc1.z += buf1.z; acc1.w += buf1.w; }
    if (rem > 2) { acc0.x += buf2.x; acc0.y += buf2.y; acc0.z += buf2.z; acc0.w += buf2.w; }

    float4 acc = make_float4(acc0.x + acc1.x, acc0.y + acc1.y,
                             acc0.z + acc1.z, acc0.w + acc1.w);
    part[grp][l64] = acc;
    __syncthreads();

    if (cnt > 0) {
        int col = tid >> 2, comp = tid & 3;
        const float* q0 = reinterpret_cast<const float*>(&part[0][col]);
        const float* q1 = reinterpret_cast<const float*>(&part[1][col]);
        const float* q2 = reinterpret_cast<const float*>(&part[2][col]);
        const float* q3 = reinterpret_cast<const float*>(&part[3][col]);
        float vsum = (q0[comp] + q1[comp]) + (q2[comp] + q3[comp]);
        atomicAdd(&out[(size_t)b * D + tid], vsum);
    }
}

// ---------------- launcher: 2 launches ----------------
extern "C" void kernel_launch(void* const* d_in, const int* in_sizes, int n_in,
                              void* d_out, int out_size) {
    const float* logits = (const float*)d_in[0];
    const float* proj = (const float*)d_in[2];
    float* out = (float*)d_out;

    int D = in_sizes[2];                 // 256
    int T = in_sizes[1];                 // 262144
    int B = out_size / D;                // 64
    int N = T / B;                       // 4096
    int K = (int)ceil(0.2 * (double)N);  // 820

    int* idxList;
    cudaGetSymbolAddress((void**)&idxList, g_idx);

    int blocksPerGraph = N / 64;         // 64 (N % 64 == 0 for this dataset)
    int grid = B * blocksPerGraph;       // 4096

    // 1) dots + fused per-graph top-K select (hidden under dot waves)
    dot_select_kernel<<<grid, 512>>>(logits, proj, out, N, K, D, blocksPerGraph);

    // 2) gather + segment sum
    gather_sum_kernel<<<B * GSPLIT, 256>>>(logits, idxList, out, K, D, 0);
}

// round 13
// speedup vs baseline: 1.0599x; 1.0599x over previous
#include <cuda_runtime.h>
#include <math.h>

// ---------------- scratch (no allocs allowed) ----------------
#define MAX_T (64 * 4096)
#define MAX_B 64
#define MAX_K 1024
__device__ float g_dot[MAX_T];          // per-node dot(logits, proj)
__device__ int   g_idx[MAX_B * MAX_K];  // selected global node indices per graph

// ---------------- kernel 1: per-row dot product ----------------
// One warp per 4 rows; all 8 float4 loads issued before reduction (MLP=8).
// 512 threads/block = 16 warps = 64 rows/block.
__global__ void __launch_bounds__(512)
dot_kernel(const float* __restrict__ logits,
           const float* __restrict__ proj,
           float* __restrict__ dots,
           int rowBase, int rowEnd) {
    __shared__ float4 pS[64];
    int tid = threadIdx.x;
    if (tid < 64) pS[tid] = reinterpret_cast<const float4*>(proj)[tid];
    __syncthreads();

    int warp = tid >> 5, lane = tid & 31;
    int row0 = rowBase + (blockIdx.x * 16 + warp) * 4;
    if (row0 >= rowEnd) return;

    const float4* rp = reinterpret_cast<const float4*>(logits) + (size_t)row0 * 64;

    float4 a[4], c[4];
#pragma unroll
    for (int r = 0; r < 4; r++) {
        a[r] = rp[(size_t)r * 64 + lane];
        c[r] = rp[(size_t)r * 64 + lane + 32];
    }
    float4 pa = pS[lane];
    float4 pc = pS[lane + 32];

    float s[4];
#pragma unroll
    for (int r = 0; r < 4; r++) {
        s[r] = a[r].x * pa.x + a[r].y * pa.y + a[r].z * pa.z + a[r].w * pa.w
             + c[r].x * pc.x + c[r].y * pc.y + c[r].z * pc.z + c[r].w * pc.w;
#pragma unroll
        for (int o = 16; o; o >>= 1) s[r] += __shfl_xor_sync(0xFFFFFFFFu, s[r], o);
    }
    if (lane < 4) dots[row0 + lane] = s[lane];
}

// ---------------- kernel 2: per-graph radix select (1024 thr, warp-aggregated) ----
__global__ void __launch_bounds__(1024)
select_kernel(const float* __restrict__ dots,
              int* __restrict__ idxList,
              float* __restrict__ out,
              int N, int K, int D, int bBase) {
    __shared__ unsigned keys[4096];
    __shared__ unsigned hist[256];
    __shared__ unsigned warpTot[8];
    __shared__ unsigned s_chosen;
    __shared__ unsigned s_need;
    __shared__ int cntGT, cntEQ;

    int b = bBase + blockIdx.x, tid = threadIdx.x;
    int lane = tid & 31, warp = tid >> 5;
    const float* d = dots + (size_t)b * N;

    for (int i = tid; i < D; i += blockDim.x) out[(size_t)b * D + i] = 0.0f;

    for (int i = tid; i < N; i += blockDim.x) {
        unsigned u = __float_as_uint(d[i]);
        u ^= (u >> 31) ? 0xFFFFFFFFu : 0x80000000u;  // order-preserving
        keys[i] = u;
    }
    if (tid == 0) s_need = (unsigned)K;
    __syncthreads();

    unsigned prefix = 0, mask = 0;
#pragma unroll
    for (int pass = 0; pass < 4; pass++) {
        int shift = 24 - 8 * pass;
        unsigned need = s_need;
        if (tid < 256) hist[tid] = 0;
        __syncthreads();
        for (int i = tid; i < N; i += blockDim.x) {
            unsigned kk = keys[i];
            bool pred = ((kk & mask) == prefix);
            unsigned bin = (kk >> shift) & 0xFFu;
            unsigned act = __ballot_sync(0xFFFFFFFFu, pred);
            if (pred) {
                unsigned mm = __match_any_sync(act, bin);
                int leader = __ffs(mm) - 1;
                if (lane == leader) atomicAdd(&hist[bin], (unsigned)__popc(mm));
            }
        }
        __syncthreads();
        if (warp < 8) {
            unsigned sum = hist[warp * 32 + lane];
#pragma unroll
            for (int o = 1; o < 32; o <<= 1) {
                unsigned t = __shfl_down_sync(0xFFFFFFFFu, sum, o);
                if (lane + o < 32) sum += t;
            }
            if (lane == 0) warpTot[warp] = sum;
            __syncwarp();
            hist[warp * 32 + lane] = sum;   // intra-warp inclusive suffix
        }
        __syncthreads();
        if (tid < 256) {
            unsigned add = 0;
            int myw = tid >> 5;
#pragma unroll
            for (int w = 0; w < 8; w++)
                if (w > myw) add += warpTot[w];
            unsigned st = hist[tid] + add;
            unsigned sn;
            if (tid == 255) sn = 0;
            else if ((tid & 31) == 31) sn = add;
            else sn = hist[tid + 1] + add;
            if (st >= need && sn < need) {
                s_chosen = (unsigned)tid;
                s_need = need - sn;
            }
        }
        __syncthreads();
        prefix |= s_chosen << shift;
        mask   |= 0xFFu << shift;
        __syncthreads();
    }

    unsigned thr = prefix;  // exact key of the k-th largest
    if (tid == 0) {
        cntGT = 0;
        cntEQ = K - (int)s_need;  // ties fill [G, K)
    }
    __syncthreads();

    int* lst = idxList + (size_t)b * K;
    unsigned lmLT = (1u << lane) - 1u;
    for (int i = tid; i < N; i += blockDim.x) {
        unsigned kk = keys[i];
        bool isGT = (kk > thr), isEQ = (kk == thr);
        unsigned bGT = __ballot_sync(0xFFFFFFFFu, isGT);
        if (bGT) {
            int base = 0;
            int leader = __ffs(bGT) - 1;
            if (lane == leader) base = atomicAdd(&cntGT, __popc(bGT));
            base = __shfl_sync(0xFFFFFFFFu, base, leader);
            if (isGT) lst[base + __popc(bGT & lmLT)] = b * N + i;
        }
        unsigned bEQ = __ballot_sync(0xFFFFFFFFu, isEQ);
        if (bEQ) {
            int base = 0;
            int leader = __ffs(bEQ) - 1;
            if (lane == leader) base = atomicAdd(&cntEQ, __popc(bEQ));
            base = __shfl_sync(0xFFFFFFFFu, base, leader);
            if (isEQ) {
                int p = base + __popc(bEQ & lmLT);
                if (p < K) lst[p] = b * N + i;
            }
        }
    }
}

// ---------------- kernel 3: gather + segment sum (direct-index, no staging) ------
// GSPLIT=32 -> 2048 blocks, 26 rows/slice. 256 threads = 4 row-groups x 64
// lanes; group g owns rows g, g+4, ... (<=7). Indices are loaded DIRECTLY by
// every thread (64 threads/group hit the same address -> L1 broadcast; the 7
// index loads are independent, MLP=7), then all <=7 row float4 loads issue as
// one predicated wave. No smem staging, no pre-load barrier.
#define GSPLIT 32
__global__ void __launch_bounds__(256)
gather_sum_kernel(const float* __restrict__ logits,
                  const int* __restrict__ idxList,
                  float* __restrict__ out,
                  int K, int D, int bBase) {
    __shared__ float4 part[4][64];

    int b = bBase + blockIdx.x / GSPLIT;
    int s = blockIdx.x % GSPLIT;
    int tid = threadIdx.x;
    int grp = tid >> 6;        // 0..3
    int l64 = tid & 63;        // float4 column within row

    int per = (K + GSPLIT - 1) / GSPLIT;          // 26 for K=820
    int r0 = s * per;
    int cnt = min(K, r0 + per) - r0;              // 14..26, always > 0 here

    const int* lst = idxList + (size_t)b * K + r0;

    // wave 1: independent index loads (broadcast within group)
    int rows[7];
#pragma unroll
    for (int j = 0; j < 7; j++) {
        int r = grp + 4 * j;
        if (r < cnt) rows[j] = __ldg(&lst[r]);
    }

    const float4* lg4 = reinterpret_cast<const float4*>(logits);
    int nD4 = D >> 2;  // 64

    // wave 2: all row loads in one predicated burst
    float4 v[7];
#pragma unroll
    for (int j = 0; j < 7; j++) {
        int r = grp + 4 * j;
        if (r < cnt) v[j] = lg4[(size_t)rows[j] * nD4 + l64];
    }

    float4 acc = make_float4(0.f, 0.f, 0.f, 0.f);
#pragma unroll
    for (int j = 0; j < 7; j++) {
        int r = grp + 4 * j;
        if (r < cnt) {
            acc.x += v[j].x; acc.y += v[j].y;
            acc.z += v[j].z; acc.w += v[j].w;
        }
    }
    part[grp][l64] = acc;
    __syncthreads();

    // thread tid owns output float tid: float4 col = tid>>2, comp = tid&3
    int col = tid >> 2, comp = tid & 3;
    const float* q0 = reinterpret_cast<const float*>(&part[0][col]);
    const float* q1 = reinterpret_cast<const float*>(&part[1][col]);
    const float* q2 = reinterpret_cast<const float*>(&part[2][col]);
    const float* q3 = reinterpret_cast<const float*>(&part[3][col]);
    float vsum = (q0[comp] + q1[comp]) + (q2[comp] + q3[comp]);
    atomicAdd(&out[(size_t)b * D + tid], vsum);
}

// ---------------- launcher: clean sequential pipeline ----------------
extern "C" void kernel_launch(void* const* d_in, const int* in_sizes, int n_in,
                              void* d_out, int out_size) {
    const float* logits = (const float*)d_in[0];
    const float* proj = (const float*)d_in[2];
    float* out = (float*)d_out;

    int D = in_sizes[2];                 // 256
    int T = in_sizes[1];                 // 262144
    int B = out_size / D;                // 64
    int N = T / B;                       // 4096
    int K = (int)ceil(0.2 * (double)N);  // 820

    float* dots;
    int* idxList;
    cudaGetSymbolAddress((void**)&dots, g_dot);
    cudaGetSymbolAddress((void**)&idxList, g_idx);

    // 1) per-node dot products (monotone proxy for sigmoid score)
    dot_kernel<<<(T + 63) / 64, 512>>>(logits, proj, dots, 0, T);

    // 2) per-graph exact top-K selection (also zeroes out)
    select_kernel<<<B, 1024>>>(dots, idxList, out, N, K, D, 0);

    // 3) gather + segment sum
    gather_sum_kernel<<<B * GSPLIT, 256>>>(logits, idxList, out, K, D, 0);
}